// round 11
// baseline (speedup 1.0000x reference)
#include <cuda_runtime.h>
#include <cuda_bf16.h>
#include <cstdint>

// Problem constants
#define MM 1024
#define NN 4096
#define KK 4096
#define HH 32
#define DD 128
#define PP 4096
#define LL (PP + MM)   // 5120

// ---------------- scratch (__device__ globals per alloc rules) ----------------
__device__ __nv_bfloat16 g_Xhi[MM * KK];
__device__ __nv_bfloat16 g_Xlo[MM * KK];
__device__ __nv_bfloat16 g_Wthi[3ull * NN * KK];   // W transposed: [z][n][k]
__device__ __nv_bfloat16 g_Wtlo[3ull * NN * KK];
__device__ __nv_bfloat16 g_Qhi[MM * NN];           // [m][h*128+d]
__device__ __nv_bfloat16 g_Qlo[MM * NN];
__device__ __nv_bfloat16 g_Khi[(size_t)HH * LL * DD];  // [h][p][d]
__device__ __nv_bfloat16 g_Klo[(size_t)HH * LL * DD];
__device__ __nv_bfloat16 g_Vhi[(size_t)HH * LL * DD];
__device__ __nv_bfloat16 g_Vlo[(size_t)HH * LL * DD];

// ================= helpers =================
__device__ __forceinline__ uint32_t smem_to_u32(const void* p) {
    uint32_t a;
    asm("{ .reg .u64 t; cvta.to.shared.u64 t, %1; cvt.u32.u64 %0, t; }" : "=r"(a) : "l"(p));
    return a;
}
__device__ __forceinline__ void cp_async16(uint32_t saddr, const void* gaddr) {
    asm volatile("cp.async.cg.shared.global [%0], [%1], 16;" :: "r"(saddr), "l"(gaddr) : "memory");
}
#define CP_COMMIT() asm volatile("cp.async.commit_group;" ::: "memory")
#define CP_WAIT(n)  asm volatile("cp.async.wait_group %0;" :: "n"(n) : "memory")

__device__ __forceinline__ void ldsm_x4(uint32_t* r, uint32_t addr) {
    asm volatile("ldmatrix.sync.aligned.m8n8.x4.shared.b16 {%0,%1,%2,%3}, [%4];"
                 : "=r"(r[0]), "=r"(r[1]), "=r"(r[2]), "=r"(r[3]) : "r"(addr));
}
__device__ __forceinline__ void ldsm_x4t(uint32_t* r, uint32_t addr) {
    asm volatile("ldmatrix.sync.aligned.m8n8.x4.trans.shared.b16 {%0,%1,%2,%3}, [%4];"
                 : "=r"(r[0]), "=r"(r[1]), "=r"(r[2]), "=r"(r[3]) : "r"(addr));
}
__device__ __forceinline__ void mma16816(float* d, const uint32_t* a, const uint32_t* b) {
    asm volatile(
        "mma.sync.aligned.m16n8k16.row.col.f32.bf16.bf16.f32 "
        "{%0,%1,%2,%3}, {%4,%5,%6,%7}, {%8,%9}, {%0,%1,%2,%3};"
        : "+f"(d[0]), "+f"(d[1]), "+f"(d[2]), "+f"(d[3])
        : "r"(a[0]), "r"(a[1]), "r"(a[2]), "r"(a[3]), "r"(b[0]), "r"(b[1]));
}
__device__ __forceinline__ uint32_t pkbf(float x, float y) {
    __nv_bfloat162 t;
    t.x = __float2bfloat16(x);
    t.y = __float2bfloat16(y);
    return *reinterpret_cast<uint32_t*>(&t);
}

// ================= conversion kernels =================
__global__ __launch_bounds__(256)
void convert_x_kernel(const float* __restrict__ X) {
    int i = (blockIdx.x * 256 + threadIdx.x) * 4;
    float4 v = *(const float4*)(X + i);
    float f[4] = {v.x, v.y, v.z, v.w};
    __align__(8) __nv_bfloat16 hi[4];
    __align__(8) __nv_bfloat16 lo[4];
#pragma unroll
    for (int j = 0; j < 4; j++) {
        hi[j] = __float2bfloat16(f[j]);
        lo[j] = __float2bfloat16(f[j] - __bfloat162float(hi[j]));
    }
    *(uint2*)&g_Xhi[i] = *(uint2*)hi;
    *(uint2*)&g_Xlo[i] = *(uint2*)lo;
}

__global__ __launch_bounds__(256)
void convert_w_kernel(const float* __restrict__ Wq, const float* __restrict__ Wk,
                      const float* __restrict__ Wv) {
    const int z = blockIdx.z;
    const float* W = (z == 0) ? Wq : (z == 1) ? Wk : Wv;
    __shared__ float t[32][33];
    const int n0 = blockIdx.x * 32;
    const int k0 = blockIdx.y * 32;
    const int tx = threadIdx.x;
    const int ty = threadIdx.y;
#pragma unroll
    for (int i = 0; i < 4; i++)
        t[ty + i * 8][tx] = W[(size_t)(k0 + ty + i * 8) * NN + n0 + tx];
    __syncthreads();
    size_t base = (size_t)z * NN * KK;
#pragma unroll
    for (int i = 0; i < 4; i++) {
        int r = ty + i * 8;
        float v = t[tx][r];
        __nv_bfloat16 h = __float2bfloat16(v);
        __nv_bfloat16 l = __float2bfloat16(v - __bfloat162float(h));
        size_t o = base + (size_t)(n0 + r) * KK + k0 + tx;
        g_Wthi[o] = h;
        g_Wtlo[o] = l;
    }
}

__global__ __launch_bounds__(256)
void convert_cache_kernel(const float* __restrict__ cK, const float* __restrict__ cV) {
    const float* src = (blockIdx.y == 0) ? cK : cV;
    __nv_bfloat16* dhi = (blockIdx.y == 0) ? g_Khi : g_Vhi;
    __nv_bfloat16* dlo = (blockIdx.y == 0) ? g_Klo : g_Vlo;
    size_t i = ((size_t)blockIdx.x * 256 + threadIdx.x) * 4;
    float4 v = *(const float4*)(src + i);
    float f[4] = {v.x, v.y, v.z, v.w};
    __align__(8) __nv_bfloat16 hi[4];
    __align__(8) __nv_bfloat16 lo[4];
#pragma unroll
    for (int j = 0; j < 4; j++) {
        hi[j] = __float2bfloat16(f[j]);
        lo[j] = __float2bfloat16(f[j] - __bfloat162float(hi[j]));
    }
    size_t h = i >> 19;
    size_t inner = i & ((size_t)(PP * DD) - 1);
    size_t o = h * ((size_t)LL * DD) + inner;
    *(uint2*)&dhi[o] = *(uint2*)hi;
    *(uint2*)&dlo[o] = *(uint2*)lo;
}

// ================= split-bf16 mma.sync GEMM: proj = X @ W =================
// grid = (NN/128, MM/128, 3); block = 256 (2x4 warps); 3-stage cp.async ring
#define GBM 128
#define GBN 128
#define GBK 32
#define NCHUNK (KK / GBK)

#define ST_AHI 0
#define ST_ALO 8192
#define ST_BHI 16384
#define ST_BLO 24576
#define STAGE_SZ 32768
#define GEMM_SMEM (3 * STAGE_SZ)

__device__ __forceinline__ uint32_t sw_off32(int row, int seg) {   // [rows][32 bf16] 64B rows
    return (uint32_t)(row * 64 + ((seg ^ (row & 3)) << 4));
}

__global__ __launch_bounds__(256, 2)
void qkv_gemm_mma() {
    extern __shared__ char smem[];
    const uint32_t sb = smem_to_u32(smem);
    const int tid = threadIdx.x;
    const int wid = tid >> 5;
    const int lane = tid & 31;
    const int wm = wid >> 2;
    const int wn = wid & 3;
    const int z = blockIdx.z;
    const int row0 = blockIdx.y * GBM;
    const int col0 = blockIdx.x * GBN;
    const int head = blockIdx.x;

    const __nv_bfloat16* Ahi = g_Xhi + (size_t)row0 * KK;
    const __nv_bfloat16* Alo = g_Xlo + (size_t)row0 * KK;
    const __nv_bfloat16* Bhi = g_Wthi + (size_t)z * NN * KK + (size_t)col0 * KK;
    const __nv_bfloat16* Blo = g_Wtlo + (size_t)z * NN * KK + (size_t)col0 * KK;

    const int lr0 = tid >> 2, ls0 = (tid & 3);
    const int lr1 = (tid + 256) >> 2, ls1 = ls0;

    auto load_stage = [&](int s, int k0) {
        uint32_t stb = sb + s * STAGE_SZ;
        const size_t go0 = (size_t)lr0 * KK + k0 + ls0 * 8;
        const size_t go1 = (size_t)lr1 * KK + k0 + ls1 * 8;
        uint32_t so0 = sw_off32(lr0, ls0), so1 = sw_off32(lr1, ls1);
        cp_async16(stb + ST_AHI + so0, Ahi + go0);
        cp_async16(stb + ST_AHI + so1, Ahi + go1);
        cp_async16(stb + ST_ALO + so0, Alo + go0);
        cp_async16(stb + ST_ALO + so1, Alo + go1);
        cp_async16(stb + ST_BHI + so0, Bhi + go0);
        cp_async16(stb + ST_BHI + so1, Bhi + go1);
        cp_async16(stb + ST_BLO + so0, Blo + go0);
        cp_async16(stb + ST_BLO + so1, Blo + go1);
    };

    float acc[4][4][4] = {};

    load_stage(0, 0);
    CP_COMMIT();
    load_stage(1, GBK);
    CP_COMMIT();

    // per-lane ldmatrix address components
    const int a_row = (lane & 15);
    const int a_seg = (lane >> 4);
    const int b_row4 = ((lane >> 4) & 1) * 8 + (lane & 7);   // x4: pair of n-frags
    const int b_seg4 = (lane >> 3) & 1;

    int s = 0, sl = 2;
    for (int c = 0; c < NCHUNK; ++c) {
        CP_WAIT(1);                 // positional: all but most recent group done -> chunk c ready
        __syncthreads();            // visibility + stage-reuse guard
        if (c + 2 < NCHUNK) load_stage(sl, (c + 2) * GBK);
        CP_COMMIT();                // always commit (empty at tail keeps positions aligned)

        const uint32_t stb = sb + s * STAGE_SZ;
#pragma unroll
        for (int ks = 0; ks < 2; ++ks) {
            const int segb = ks * 2;
            uint32_t ahi[4][4], alo[4][4], bhi[2][4], blo[2][4];
#pragma unroll
            for (int mf = 0; mf < 4; ++mf) {
                uint32_t off = sw_off32(wm * 64 + mf * 16 + a_row, segb + a_seg);
                ldsm_x4(ahi[mf], stb + ST_AHI + off);
                ldsm_x4(alo[mf], stb + ST_ALO + off);
            }
#pragma unroll
            for (int np = 0; np < 2; ++np) {
                uint32_t off = sw_off32(wn * 32 + np * 16 + b_row4, segb + b_seg4);
                ldsm_x4(bhi[np], stb + ST_BHI + off);
                ldsm_x4(blo[np], stb + ST_BLO + off);
            }
#pragma unroll
            for (int mf = 0; mf < 4; ++mf)
#pragma unroll
                for (int nf = 0; nf < 4; ++nf) {
                    const uint32_t* bh = bhi[nf >> 1] + (nf & 1) * 2;
                    const uint32_t* bl = blo[nf >> 1] + (nf & 1) * 2;
                    mma16816(acc[mf][nf], ahi[mf], bh);
                    mma16816(acc[mf][nf], ahi[mf], bl);
                    mma16816(acc[mf][nf], alo[mf], bh);
                }
        }
        s = (s == 2) ? 0 : s + 1;
        sl = (sl == 2) ? 0 : sl + 1;
    }

    // epilogue: write split-bf16 directly
    const int erow = lane >> 2;
    const int ecol = (lane & 3) * 2;
#pragma unroll
    for (int mf = 0; mf < 4; ++mf) {
#pragma unroll
        for (int nf = 0; nf < 4; ++nf) {
            int cloc = wn * 32 + nf * 8 + ecol;
#pragma unroll
            for (int rr = 0; rr < 2; ++rr) {
                int rowg = row0 + wm * 64 + mf * 16 + erow + rr * 8;
                float v0 = acc[mf][nf][rr * 2 + 0];
                float v1 = acc[mf][nf][rr * 2 + 1];
                __nv_bfloat16 h0 = __float2bfloat16(v0);
                __nv_bfloat16 h1 = __float2bfloat16(v1);
                float l0 = v0 - __bfloat162float(h0);
                float l1 = v1 - __bfloat162float(h1);
                uint32_t ph = pkbf(__bfloat162float(h0), __bfloat162float(h1));
                uint32_t pl = pkbf(l0, l1);
                if (z == 0) {
                    size_t o = (size_t)rowg * NN + col0 + cloc;
                    *(uint32_t*)&g_Qhi[o] = ph;
                    *(uint32_t*)&g_Qlo[o] = pl;
                } else {
                    size_t o = ((size_t)head * LL + PP + rowg) * DD + cloc;
                    if (z == 1) { *(uint32_t*)&g_Khi[o] = ph; *(uint32_t*)&g_Klo[o] = pl; }
                    else        { *(uint32_t*)&g_Vhi[o] = ph; *(uint32_t*)&g_Vlo[o] = pl; }
                }
            }
        }
    }
}

// ================= tensor-core flash attention (split bf16, 3-pass) =================
// grid = (MM/64, HH); block = 128 (4 warps); smem 96KB, 2 CTAs/SM
#define ABQ 64
#define ATK 64
#define NT_KV (LL / ATK)   // 80

#define AQH 0
#define AQL 16384
#define AKH 32768
#define AKL 49152
#define AVH 65536
#define AVL 81920
#define ATTN_SMEM 98304

__device__ __forceinline__ uint32_t sw_off128(int row, int seg) {  // [rows][128 bf16] 256B rows
    return (uint32_t)(row * 256 + ((seg ^ (row & 7)) << 4));
}

__global__ __launch_bounds__(128, 2)
void attn_mma_kernel(float* __restrict__ out) {
    extern __shared__ char smem[];
    const uint32_t sb = smem_to_u32(smem);
    const int tid = threadIdx.x;
    const int lane = tid & 31;
    const int wq = tid >> 5;
    const int h = blockIdx.y;
    const int q0 = blockIdx.x * ABQ;

    const __nv_bfloat16* Kh = g_Khi + (size_t)h * LL * DD;
    const __nv_bfloat16* Kl = g_Klo + (size_t)h * LL * DD;
    const __nv_bfloat16* Vh = g_Vhi + (size_t)h * LL * DD;
    const __nv_bfloat16* Vl = g_Vlo + (size_t)h * LL * DD;

    // Q load (group 0)
#pragma unroll
    for (int i = 0; i < 8; i++) {
        int idx = tid + i * 128;
        int row = idx >> 4, seg = idx & 15;
        uint32_t so = sw_off128(row, seg);
        size_t go = (size_t)(q0 + row) * NN + h * DD + seg * 8;
        cp_async16(sb + AQH + so, g_Qhi + go);
        cp_async16(sb + AQL + so, g_Qlo + go);
    }
    CP_COMMIT();

    auto load_kv = [&](uint32_t dH, uint32_t dL, const __nv_bfloat16* sH,
                       const __nv_bfloat16* sL, int p0) {
#pragma unroll
        for (int i = 0; i < 8; i++) {
            int idx = tid + i * 128;
            int row = idx >> 4, seg = idx & 15;
            uint32_t so = sw_off128(row, seg);
            size_t go = (size_t)(p0 + row) * DD + seg * 8;
            cp_async16(dH + so, sH + go);
            cp_async16(dL + so, sL + go);
        }
    };

    load_kv(sb + AKH, sb + AKL, Kh, Kl, 0);  CP_COMMIT();   // K0
    load_kv(sb + AVH, sb + AVL, Vh, Vl, 0);  CP_COMMIT();   // V0

    float oacc[16][4] = {};
    float m_s[2] = {-1e30f, -1e30f};
    float l_s[2] = {0.0f, 0.0f};

    const int a_row = wq * 16 + (lane & 15);
    const int b_row = ((lane >> 4) & 1) * 8 + (lane & 7);
    const int bsegl = (lane >> 3) & 1;
    const int v_row = ((lane >> 3) & 1) * 8 + (lane & 7);
    const int v_seg = lane >> 4;

    for (int t = 0; t < NT_KV; ++t) {
        CP_WAIT(1);                 // K(t) ready (V(t) may be in flight)
        __syncthreads();

        // ---- S = Q K^T tile (16 x 64 per warp), 3-pass split ----
        float sacc[8][4] = {};
#pragma unroll
        for (int ksd = 0; ksd < 8; ++ksd) {
            uint32_t ah[4], al[4];
            uint32_t aoff = sw_off128(a_row, ksd * 2 + (lane >> 4));
            ldsm_x4(ah, sb + AQH + aoff);
            ldsm_x4(al, sb + AQL + aoff);
#pragma unroll
            for (int j = 0; j < 4; ++j) {
                uint32_t bh[4], bl[4];
                uint32_t boff = sw_off128(j * 16 + b_row, ksd * 2 + bsegl);
                ldsm_x4(bh, sb + AKH + boff);
                ldsm_x4(bl, sb + AKL + boff);
                mma16816(sacc[2 * j], ah, bh);
                mma16816(sacc[2 * j], ah, bl);
                mma16816(sacc[2 * j], al, bh);
                mma16816(sacc[2 * j + 1], ah, bh + 2);
                mma16816(sacc[2 * j + 1], ah, bl + 2);
                mma16816(sacc[2 * j + 1], al, bh + 2);
            }
        }
        __syncthreads();            // all warps done reading K(t)
        if (t + 1 < NT_KV) load_kv(sb + AKH, sb + AKL, Kh, Kl, (t + 1) * ATK);
        CP_COMMIT();                // K(t+1) (or empty)

        // ---- online softmax + P conversion (registers only; overlaps K(t+1) load) ----
        uint32_t pa_hi[16], pa_lo[16];
#pragma unroll
        for (int rh = 0; rh < 2; ++rh) {
            float mx = -1e30f;
#pragma unroll
            for (int nt = 0; nt < 8; ++nt)
                mx = fmaxf(mx, fmaxf(sacc[nt][rh * 2], sacc[nt][rh * 2 + 1]));
            mx = fmaxf(mx, __shfl_xor_sync(0xffffffffu, mx, 1));
            mx = fmaxf(mx, __shfl_xor_sync(0xffffffffu, mx, 2));
            float mnew = fmaxf(m_s[rh], mx);
            float sc = __expf(m_s[rh] - mnew);
            m_s[rh] = mnew;
            float sum = 0.0f;
#pragma unroll
            for (int nt = 0; nt < 8; ++nt) {
                float e0 = __expf(sacc[nt][rh * 2] - mnew);
                float e1 = __expf(sacc[nt][rh * 2 + 1] - mnew);
                sacc[nt][rh * 2] = e0;
                sacc[nt][rh * 2 + 1] = e1;
                sum += e0 + e1;
            }
            sum += __shfl_xor_sync(0xffffffffu, sum, 1);
            sum += __shfl_xor_sync(0xffffffffu, sum, 2);
            l_s[rh] = l_s[rh] * sc + sum;
#pragma unroll
            for (int dt = 0; dt < 16; ++dt) {
                oacc[dt][rh * 2] *= sc;
                oacc[dt][rh * 2 + 1] *= sc;
            }
        }
#pragma unroll
        for (int ks = 0; ks < 4; ++ks) {
#pragma unroll
            for (int half = 0; half < 2; ++half) {
                int nt = 2 * ks + half;
#pragma unroll
                for (int rh = 0; rh < 2; ++rh) {
                    float v0 = sacc[nt][rh * 2], v1 = sacc[nt][rh * 2 + 1];
                    __nv_bfloat16 h0 = __float2bfloat16(v0);
                    __nv_bfloat16 h1 = __float2bfloat16(v1);
                    pa_hi[ks * 4 + half * 2 + rh] = pkbf(__bfloat162float(h0), __bfloat162float(h1));
                    pa_lo[ks * 4 + half * 2 + rh] =
                        pkbf(v0 - __bfloat162float(h0), v1 - __bfloat162float(h1));
                }
            }
        }

        CP_WAIT(1);                 // V(t) ready (K(t+1) may be in flight)
        __syncthreads();

        // ---- O += P V (3-pass split) ----
#pragma unroll
        for (int ks = 0; ks < 4; ++ks) {
            const uint32_t* ph = pa_hi + ks * 4;
            const uint32_t* pl = pa_lo + ks * 4;
#pragma unroll
            for (int dt2 = 0; dt2 < 8; ++dt2) {
                uint32_t vh[4], vl[4];
                uint32_t voff = sw_off128(ks * 16 + v_row, dt2 * 2 + v_seg);
                ldsm_x4t(vh, sb + AVH + voff);
                ldsm_x4t(vl, sb + AVL + voff);
                mma16816(oacc[2 * dt2], ph, vh);
                mma16816(oacc[2 * dt2], ph, vl);
                mma16816(oacc[2 * dt2], pl, vh);
                mma16816(oacc[2 * dt2 + 1], ph, vh + 2);
                mma16816(oacc[2 * dt2 + 1], ph, vl + 2);
                mma16816(oacc[2 * dt2 + 1], pl, vh + 2);
            }
        }
        __syncthreads();            // all warps done reading V(t)
        if (t + 1 < NT_KV) load_kv(sb + AVH, sb + AVL, Vh, Vl, (t + 1) * ATK);
        CP_COMMIT();                // V(t+1) (or empty)
    }

    // ---- epilogue ----
    const int g = lane >> 2;
    const int tg = lane & 3;
    float inv0 = 1.0f / l_s[0];
    float inv1 = 1.0f / l_s[1];
    int row0 = q0 + wq * 16 + g;
#pragma unroll
    for (int dt = 0; dt < 16; ++dt) {
        int col = h * DD + dt * 8 + tg * 2;
        *(float2*)&out[(size_t)row0 * NN + col] =
            make_float2(oacc[dt][0] * inv0, oacc[dt][1] * inv0);
        *(float2*)&out[(size_t)(row0 + 8) * NN + col] =
            make_float2(oacc[dt][2] * inv1, oacc[dt][3] * inv1);
    }
}

// ================= launch =================
extern "C" void kernel_launch(void* const* d_in, const int* in_sizes, int n_in,
                              void* d_out, int out_size) {
    const float* X  = (const float*)d_in[0];
    const float* Wq = (const float*)d_in[1];
    const float* Wk = (const float*)d_in[2];
    const float* Wv = (const float*)d_in[3];
    const float* cK = (const float*)d_in[4];
    const float* cV = (const float*)d_in[5];
    float* out = (float*)d_out;

    convert_x_kernel<<<(MM * KK) / (4 * 256), 256>>>(X);
    dim3 gw(NN / 32, KK / 32, 3);
    convert_w_kernel<<<gw, dim3(32, 8)>>>(Wq, Wk, Wv);
    dim3 gc((unsigned)(((size_t)HH * PP * DD) / (4 * 256)), 2);
    convert_cache_kernel<<<gc, 256>>>(cK, cV);

    cudaFuncSetAttribute(qkv_gemm_mma, cudaFuncAttributeMaxDynamicSharedMemorySize, GEMM_SMEM);
    dim3 gg(NN / GBN, MM / GBM, 3);
    qkv_gemm_mma<<<gg, 256, GEMM_SMEM>>>();

    cudaFuncSetAttribute(attn_mma_kernel, cudaFuncAttributeMaxDynamicSharedMemorySize, ATTN_SMEM);
    dim3 ga(MM / ABQ, HH);
    attn_mma_kernel<<<ga, 128, ATTN_SMEM>>>(out);
}

// round 12
// speedup vs baseline: 1.0010x; 1.0010x over previous
#include <cuda_runtime.h>
#include <cuda_bf16.h>
#include <cstdint>

// Problem constants
#define MM 1024
#define NN 4096
#define KK 4096
#define HH 32
#define DD 128
#define PP 4096
#define LL (PP + MM)   // 5120

// ---------------- scratch (__device__ globals per alloc rules) ----------------
__device__ __nv_bfloat16 g_Xhi[MM * KK];
__device__ __nv_bfloat16 g_Xlo[MM * KK];
__device__ __nv_bfloat16 g_Wthi[3ull * NN * KK];   // W transposed: [z][n][k]
__device__ __nv_bfloat16 g_Wtlo[3ull * NN * KK];
__device__ __nv_bfloat16 g_Qhi[MM * NN];           // [m][h*128+d]
__device__ __nv_bfloat16 g_Qlo[MM * NN];
__device__ __nv_bfloat16 g_Khi[(size_t)HH * LL * DD];  // [h][p][d]
__device__ __nv_bfloat16 g_Klo[(size_t)HH * LL * DD];
__device__ __nv_bfloat16 g_Vhi[(size_t)HH * LL * DD];
__device__ __nv_bfloat16 g_Vlo[(size_t)HH * LL * DD];

// ================= helpers =================
__device__ __forceinline__ uint32_t smem_to_u32(const void* p) {
    uint32_t a;
    asm("{ .reg .u64 t; cvta.to.shared.u64 t, %1; cvt.u32.u64 %0, t; }" : "=r"(a) : "l"(p));
    return a;
}
__device__ __forceinline__ void cp_async16(uint32_t saddr, const void* gaddr) {
    asm volatile("cp.async.cg.shared.global [%0], [%1], 16;" :: "r"(saddr), "l"(gaddr) : "memory");
}
#define CP_COMMIT() asm volatile("cp.async.commit_group;" ::: "memory")
#define CP_WAIT(n)  asm volatile("cp.async.wait_group %0;" :: "n"(n) : "memory")

__device__ __forceinline__ void ldsm_x4(uint32_t* r, uint32_t addr) {
    asm volatile("ldmatrix.sync.aligned.m8n8.x4.shared.b16 {%0,%1,%2,%3}, [%4];"
                 : "=r"(r[0]), "=r"(r[1]), "=r"(r[2]), "=r"(r[3]) : "r"(addr));
}
__device__ __forceinline__ void ldsm_x4t(uint32_t* r, uint32_t addr) {
    asm volatile("ldmatrix.sync.aligned.m8n8.x4.trans.shared.b16 {%0,%1,%2,%3}, [%4];"
                 : "=r"(r[0]), "=r"(r[1]), "=r"(r[2]), "=r"(r[3]) : "r"(addr));
}
__device__ __forceinline__ void mma16816(float* d, const uint32_t* a, const uint32_t* b) {
    asm volatile(
        "mma.sync.aligned.m16n8k16.row.col.f32.bf16.bf16.f32 "
        "{%0,%1,%2,%3}, {%4,%5,%6,%7}, {%8,%9}, {%0,%1,%2,%3};"
        : "+f"(d[0]), "+f"(d[1]), "+f"(d[2]), "+f"(d[3])
        : "r"(a[0]), "r"(a[1]), "r"(a[2]), "r"(a[3]), "r"(b[0]), "r"(b[1]));
}
__device__ __forceinline__ uint32_t pkbf(float x, float y) {
    __nv_bfloat162 t;
    t.x = __float2bfloat16(x);
    t.y = __float2bfloat16(y);
    return *reinterpret_cast<uint32_t*>(&t);
}

// ================= conversion kernels =================
__global__ __launch_bounds__(256)
void convert_x_kernel(const float* __restrict__ X) {
    int i = (blockIdx.x * 256 + threadIdx.x) * 4;
    float4 v = *(const float4*)(X + i);
    float f[4] = {v.x, v.y, v.z, v.w};
    __align__(8) __nv_bfloat16 hi[4];
    __align__(8) __nv_bfloat16 lo[4];
#pragma unroll
    for (int j = 0; j < 4; j++) {
        hi[j] = __float2bfloat16(f[j]);
        lo[j] = __float2bfloat16(f[j] - __bfloat162float(hi[j]));
    }
    *(uint2*)&g_Xhi[i] = *(uint2*)hi;
    *(uint2*)&g_Xlo[i] = *(uint2*)lo;
}

__global__ __launch_bounds__(256)
void convert_w_kernel(const float* __restrict__ Wq, const float* __restrict__ Wk,
                      const float* __restrict__ Wv) {
    const int z = blockIdx.z;
    const float* W = (z == 0) ? Wq : (z == 1) ? Wk : Wv;
    __shared__ float t[32][33];
    const int n0 = blockIdx.x * 32;
    const int k0 = blockIdx.y * 32;
    const int tx = threadIdx.x;
    const int ty = threadIdx.y;
#pragma unroll
    for (int i = 0; i < 4; i++)
        t[ty + i * 8][tx] = W[(size_t)(k0 + ty + i * 8) * NN + n0 + tx];
    __syncthreads();
    size_t base = (size_t)z * NN * KK;
#pragma unroll
    for (int i = 0; i < 4; i++) {
        int r = ty + i * 8;
        float v = t[tx][r];
        __nv_bfloat16 h = __float2bfloat16(v);
        __nv_bfloat16 l = __float2bfloat16(v - __bfloat162float(h));
        size_t o = base + (size_t)(n0 + r) * KK + k0 + tx;
        g_Wthi[o] = h;
        g_Wtlo[o] = l;
    }
}

__global__ __launch_bounds__(256)
void convert_cache_kernel(const float* __restrict__ cK, const float* __restrict__ cV) {
    const float* src = (blockIdx.y == 0) ? cK : cV;
    __nv_bfloat16* dhi = (blockIdx.y == 0) ? g_Khi : g_Vhi;
    __nv_bfloat16* dlo = (blockIdx.y == 0) ? g_Klo : g_Vlo;
    size_t i = ((size_t)blockIdx.x * 256 + threadIdx.x) * 4;
    float4 v = *(const float4*)(src + i);
    float f[4] = {v.x, v.y, v.z, v.w};
    __align__(8) __nv_bfloat16 hi[4];
    __align__(8) __nv_bfloat16 lo[4];
#pragma unroll
    for (int j = 0; j < 4; j++) {
        hi[j] = __float2bfloat16(f[j]);
        lo[j] = __float2bfloat16(f[j] - __bfloat162float(hi[j]));
    }
    size_t h = i >> 19;
    size_t inner = i & ((size_t)(PP * DD) - 1);
    size_t o = h * ((size_t)LL * DD) + inner;
    *(uint2*)&dhi[o] = *(uint2*)hi;
    *(uint2*)&dlo[o] = *(uint2*)lo;
}

// ================= split-bf16 mma.sync GEMM: proj = X @ W =================
// grid = (NN/128, MM/128, 3); block = 256 (2x4 warps); 3-stage cp.async ring
#define GBM 128
#define GBN 128
#define GBK 32
#define NCHUNK (KK / GBK)

#define ST_AHI 0
#define ST_ALO 8192
#define ST_BHI 16384
#define ST_BLO 24576
#define STAGE_SZ 32768
#define GEMM_SMEM (3 * STAGE_SZ)

__device__ __forceinline__ uint32_t sw_off32(int row, int seg) {   // [rows][32 bf16] 64B rows
    return (uint32_t)(row * 64 + ((seg ^ (row & 3)) << 4));
}

__global__ __launch_bounds__(256, 2)
void qkv_gemm_mma() {
    extern __shared__ char smem[];
    const uint32_t sb = smem_to_u32(smem);
    const int tid = threadIdx.x;
    const int wid = tid >> 5;
    const int lane = tid & 31;
    const int wm = wid >> 2;
    const int wn = wid & 3;
    const int z = blockIdx.z;
    const int row0 = blockIdx.y * GBM;
    const int col0 = blockIdx.x * GBN;
    const int head = blockIdx.x;

    const __nv_bfloat16* Ahi = g_Xhi + (size_t)row0 * KK;
    const __nv_bfloat16* Alo = g_Xlo + (size_t)row0 * KK;
    const __nv_bfloat16* Bhi = g_Wthi + (size_t)z * NN * KK + (size_t)col0 * KK;
    const __nv_bfloat16* Blo = g_Wtlo + (size_t)z * NN * KK + (size_t)col0 * KK;

    const int lr0 = tid >> 2, ls0 = (tid & 3);
    const int lr1 = (tid + 256) >> 2, ls1 = ls0;

    auto load_stage = [&](int s, int k0) {
        uint32_t stb = sb + s * STAGE_SZ;
        const size_t go0 = (size_t)lr0 * KK + k0 + ls0 * 8;
        const size_t go1 = (size_t)lr1 * KK + k0 + ls1 * 8;
        uint32_t so0 = sw_off32(lr0, ls0), so1 = sw_off32(lr1, ls1);
        cp_async16(stb + ST_AHI + so0, Ahi + go0);
        cp_async16(stb + ST_AHI + so1, Ahi + go1);
        cp_async16(stb + ST_ALO + so0, Alo + go0);
        cp_async16(stb + ST_ALO + so1, Alo + go1);
        cp_async16(stb + ST_BHI + so0, Bhi + go0);
        cp_async16(stb + ST_BHI + so1, Bhi + go1);
        cp_async16(stb + ST_BLO + so0, Blo + go0);
        cp_async16(stb + ST_BLO + so1, Blo + go1);
    };

    float acc[4][4][4] = {};

    load_stage(0, 0);
    CP_COMMIT();
    load_stage(1, GBK);
    CP_COMMIT();

    // per-lane ldmatrix address components
    const int a_row = (lane & 15);
    const int a_seg = (lane >> 4);
    const int b_row4 = ((lane >> 4) & 1) * 8 + (lane & 7);   // x4: pair of n-frags
    const int b_seg4 = (lane >> 3) & 1;

    int s = 0, sl = 2;
    for (int c = 0; c < NCHUNK; ++c) {
        CP_WAIT(1);                 // positional: all but most recent group done -> chunk c ready
        __syncthreads();            // visibility + stage-reuse guard
        if (c + 2 < NCHUNK) load_stage(sl, (c + 2) * GBK);
        CP_COMMIT();                // always commit (empty at tail keeps positions aligned)

        const uint32_t stb = sb + s * STAGE_SZ;
#pragma unroll
        for (int ks = 0; ks < 2; ++ks) {
            const int segb = ks * 2;
            uint32_t ahi[4][4], alo[4][4], bhi[2][4], blo[2][4];
#pragma unroll
            for (int mf = 0; mf < 4; ++mf) {
                uint32_t off = sw_off32(wm * 64 + mf * 16 + a_row, segb + a_seg);
                ldsm_x4(ahi[mf], stb + ST_AHI + off);
                ldsm_x4(alo[mf], stb + ST_ALO + off);
            }
#pragma unroll
            for (int np = 0; np < 2; ++np) {
                uint32_t off = sw_off32(wn * 32 + np * 16 + b_row4, segb + b_seg4);
                ldsm_x4(bhi[np], stb + ST_BHI + off);
                ldsm_x4(blo[np], stb + ST_BLO + off);
            }
#pragma unroll
            for (int mf = 0; mf < 4; ++mf)
#pragma unroll
                for (int nf = 0; nf < 4; ++nf) {
                    const uint32_t* bh = bhi[nf >> 1] + (nf & 1) * 2;
                    const uint32_t* bl = blo[nf >> 1] + (nf & 1) * 2;
                    mma16816(acc[mf][nf], ahi[mf], bh);
                    mma16816(acc[mf][nf], ahi[mf], bl);
                    mma16816(acc[mf][nf], alo[mf], bh);
                }
        }
        s = (s == 2) ? 0 : s + 1;
        sl = (sl == 2) ? 0 : sl + 1;
    }

    // epilogue: write split-bf16 directly
    const int erow = lane >> 2;
    const int ecol = (lane & 3) * 2;
#pragma unroll
    for (int mf = 0; mf < 4; ++mf) {
#pragma unroll
        for (int nf = 0; nf < 4; ++nf) {
            int cloc = wn * 32 + nf * 8 + ecol;
#pragma unroll
            for (int rr = 0; rr < 2; ++rr) {
                int rowg = row0 + wm * 64 + mf * 16 + erow + rr * 8;
                float v0 = acc[mf][nf][rr * 2 + 0];
                float v1 = acc[mf][nf][rr * 2 + 1];
                __nv_bfloat16 h0 = __float2bfloat16(v0);
                __nv_bfloat16 h1 = __float2bfloat16(v1);
                float l0 = v0 - __bfloat162float(h0);
                float l1 = v1 - __bfloat162float(h1);
                uint32_t ph = pkbf(__bfloat162float(h0), __bfloat162float(h1));
                uint32_t pl = pkbf(l0, l1);
                if (z == 0) {
                    size_t o = (size_t)rowg * NN + col0 + cloc;
                    *(uint32_t*)&g_Qhi[o] = ph;
                    *(uint32_t*)&g_Qlo[o] = pl;
                } else {
                    size_t o = ((size_t)head * LL + PP + rowg) * DD + cloc;
                    if (z == 1) { *(uint32_t*)&g_Khi[o] = ph; *(uint32_t*)&g_Klo[o] = pl; }
                    else        { *(uint32_t*)&g_Vhi[o] = ph; *(uint32_t*)&g_Vlo[o] = pl; }
                }
            }
        }
    }
}

// ================= tensor-core flash attention (split bf16, 3-pass) =================
// grid = (MM/64, HH); block = 128 (4 warps); smem 96KB, 2 CTAs/SM
#define ABQ 64
#define ATK 64
#define NT_KV (LL / ATK)   // 80

#define AQH 0
#define AQL 16384
#define AKH 32768
#define AKL 49152
#define AVH 65536
#define AVL 81920
#define ATTN_SMEM 98304

__device__ __forceinline__ uint32_t sw_off128(int row, int seg) {  // [rows][128 bf16] 256B rows
    return (uint32_t)(row * 256 + ((seg ^ (row & 7)) << 4));
}

__global__ __launch_bounds__(128, 2)
void attn_mma_kernel(float* __restrict__ out) {
    extern __shared__ char smem[];
    const uint32_t sb = smem_to_u32(smem);
    const int tid = threadIdx.x;
    const int lane = tid & 31;
    const int wq = tid >> 5;
    const int h = blockIdx.y;
    const int q0 = blockIdx.x * ABQ;

    const __nv_bfloat16* Kh = g_Khi + (size_t)h * LL * DD;
    const __nv_bfloat16* Kl = g_Klo + (size_t)h * LL * DD;
    const __nv_bfloat16* Vh = g_Vhi + (size_t)h * LL * DD;
    const __nv_bfloat16* Vl = g_Vlo + (size_t)h * LL * DD;

    // Q load (group 0)
#pragma unroll
    for (int i = 0; i < 8; i++) {
        int idx = tid + i * 128;
        int row = idx >> 4, seg = idx & 15;
        uint32_t so = sw_off128(row, seg);
        size_t go = (size_t)(q0 + row) * NN + h * DD + seg * 8;
        cp_async16(sb + AQH + so, g_Qhi + go);
        cp_async16(sb + AQL + so, g_Qlo + go);
    }
    CP_COMMIT();

    auto load_kv = [&](uint32_t dH, uint32_t dL, const __nv_bfloat16* sH,
                       const __nv_bfloat16* sL, int p0) {
#pragma unroll
        for (int i = 0; i < 8; i++) {
            int idx = tid + i * 128;
            int row = idx >> 4, seg = idx & 15;
            uint32_t so = sw_off128(row, seg);
            size_t go = (size_t)(p0 + row) * DD + seg * 8;
            cp_async16(dH + so, sH + go);
            cp_async16(dL + so, sL + go);
        }
    };

    load_kv(sb + AKH, sb + AKL, Kh, Kl, 0);  CP_COMMIT();   // K0
    load_kv(sb + AVH, sb + AVL, Vh, Vl, 0);  CP_COMMIT();   // V0

    float oacc[16][4] = {};
    float m_s[2] = {-1e30f, -1e30f};
    float l_s[2] = {0.0f, 0.0f};

    const int a_row = wq * 16 + (lane & 15);
    const int b_row = ((lane >> 4) & 1) * 8 + (lane & 7);
    const int bsegl = (lane >> 3) & 1;
    const int v_row = ((lane >> 3) & 1) * 8 + (lane & 7);
    const int v_seg = lane >> 4;

    for (int t = 0; t < NT_KV; ++t) {
        CP_WAIT(1);                 // K(t) ready (V(t) may be in flight)
        __syncthreads();

        // ---- S = Q K^T tile (16 x 64 per warp), 3-pass split ----
        float sacc[8][4] = {};
#pragma unroll
        for (int ksd = 0; ksd < 8; ++ksd) {
            uint32_t ah[4], al[4];
            uint32_t aoff = sw_off128(a_row, ksd * 2 + (lane >> 4));
            ldsm_x4(ah, sb + AQH + aoff);
            ldsm_x4(al, sb + AQL + aoff);
#pragma unroll
            for (int j = 0; j < 4; ++j) {
                uint32_t bh[4], bl[4];
                uint32_t boff = sw_off128(j * 16 + b_row, ksd * 2 + bsegl);
                ldsm_x4(bh, sb + AKH + boff);
                ldsm_x4(bl, sb + AKL + boff);
                mma16816(sacc[2 * j], ah, bh);
                mma16816(sacc[2 * j], ah, bl);
                mma16816(sacc[2 * j], al, bh);
                mma16816(sacc[2 * j + 1], ah, bh + 2);
                mma16816(sacc[2 * j + 1], ah, bl + 2);
                mma16816(sacc[2 * j + 1], al, bh + 2);
            }
        }
        __syncthreads();            // all warps done reading K(t)
        if (t + 1 < NT_KV) load_kv(sb + AKH, sb + AKL, Kh, Kl, (t + 1) * ATK);
        CP_COMMIT();                // K(t+1) (or empty)

        // ---- online softmax + P conversion (registers only; overlaps K(t+1) load) ----
        uint32_t pa_hi[16], pa_lo[16];
#pragma unroll
        for (int rh = 0; rh < 2; ++rh) {
            float mx = -1e30f;
#pragma unroll
            for (int nt = 0; nt < 8; ++nt)
                mx = fmaxf(mx, fmaxf(sacc[nt][rh * 2], sacc[nt][rh * 2 + 1]));
            mx = fmaxf(mx, __shfl_xor_sync(0xffffffffu, mx, 1));
            mx = fmaxf(mx, __shfl_xor_sync(0xffffffffu, mx, 2));
            float mnew = fmaxf(m_s[rh], mx);
            float sc = __expf(m_s[rh] - mnew);
            m_s[rh] = mnew;
            float sum = 0.0f;
#pragma unroll
            for (int nt = 0; nt < 8; ++nt) {
                float e0 = __expf(sacc[nt][rh * 2] - mnew);
                float e1 = __expf(sacc[nt][rh * 2 + 1] - mnew);
                sacc[nt][rh * 2] = e0;
                sacc[nt][rh * 2 + 1] = e1;
                sum += e0 + e1;
            }
            sum += __shfl_xor_sync(0xffffffffu, sum, 1);
            sum += __shfl_xor_sync(0xffffffffu, sum, 2);
            l_s[rh] = l_s[rh] * sc + sum;
#pragma unroll
            for (int dt = 0; dt < 16; ++dt) {
                oacc[dt][rh * 2] *= sc;
                oacc[dt][rh * 2 + 1] *= sc;
            }
        }
#pragma unroll
        for (int ks = 0; ks < 4; ++ks) {
#pragma unroll
            for (int half = 0; half < 2; ++half) {
                int nt = 2 * ks + half;
#pragma unroll
                for (int rh = 0; rh < 2; ++rh) {
                    float v0 = sacc[nt][rh * 2], v1 = sacc[nt][rh * 2 + 1];
                    __nv_bfloat16 h0 = __float2bfloat16(v0);
                    __nv_bfloat16 h1 = __float2bfloat16(v1);
                    pa_hi[ks * 4 + half * 2 + rh] = pkbf(__bfloat162float(h0), __bfloat162float(h1));
                    pa_lo[ks * 4 + half * 2 + rh] =
                        pkbf(v0 - __bfloat162float(h0), v1 - __bfloat162float(h1));
                }
            }
        }

        CP_WAIT(1);                 // V(t) ready (K(t+1) may be in flight)
        __syncthreads();

        // ---- O += P V (3-pass split) ----
#pragma unroll
        for (int ks = 0; ks < 4; ++ks) {
            const uint32_t* ph = pa_hi + ks * 4;
            const uint32_t* pl = pa_lo + ks * 4;
#pragma unroll
            for (int dt2 = 0; dt2 < 8; ++dt2) {
                uint32_t vh[4], vl[4];
                uint32_t voff = sw_off128(ks * 16 + v_row, dt2 * 2 + v_seg);
                ldsm_x4t(vh, sb + AVH + voff);
                ldsm_x4t(vl, sb + AVL + voff);
                mma16816(oacc[2 * dt2], ph, vh);
                mma16816(oacc[2 * dt2], ph, vl);
                mma16816(oacc[2 * dt2], pl, vh);
                mma16816(oacc[2 * dt2 + 1], ph, vh + 2);
                mma16816(oacc[2 * dt2 + 1], ph, vl + 2);
                mma16816(oacc[2 * dt2 + 1], pl, vh + 2);
            }
        }
        __syncthreads();            // all warps done reading V(t)
        if (t + 1 < NT_KV) load_kv(sb + AVH, sb + AVL, Vh, Vl, (t + 1) * ATK);
        CP_COMMIT();                // V(t+1) (or empty)
    }

    // ---- epilogue ----
    const int g = lane >> 2;
    const int tg = lane & 3;
    float inv0 = 1.0f / l_s[0];
    float inv1 = 1.0f / l_s[1];
    int row0 = q0 + wq * 16 + g;
#pragma unroll
    for (int dt = 0; dt < 16; ++dt) {
        int col = h * DD + dt * 8 + tg * 2;
        *(float2*)&out[(size_t)row0 * NN + col] =
            make_float2(oacc[dt][0] * inv0, oacc[dt][1] * inv0);
        *(float2*)&out[(size_t)(row0 + 8) * NN + col] =
            make_float2(oacc[dt][2] * inv1, oacc[dt][3] * inv1);
    }
}

// ================= launch =================
extern "C" void kernel_launch(void* const* d_in, const int* in_sizes, int n_in,
                              void* d_out, int out_size) {
    const float* X  = (const float*)d_in[0];
    const float* Wq = (const float*)d_in[1];
    const float* Wk = (const float*)d_in[2];
    const float* Wv = (const float*)d_in[3];
    const float* cK = (const float*)d_in[4];
    const float* cV = (const float*)d_in[5];
    float* out = (float*)d_out;

    convert_x_kernel<<<(MM * KK) / (4 * 256), 256>>>(X);
    dim3 gw(NN / 32, KK / 32, 3);
    convert_w_kernel<<<gw, dim3(32, 8)>>>(Wq, Wk, Wv);
    dim3 gc((unsigned)(((size_t)HH * PP * DD) / (4 * 256)), 2);
    convert_cache_kernel<<<gc, 256>>>(cK, cV);

    cudaFuncSetAttribute(qkv_gemm_mma, cudaFuncAttributeMaxDynamicSharedMemorySize, GEMM_SMEM);
    dim3 gg(NN / GBN, MM / GBM, 3);
    qkv_gemm_mma<<<gg, 256, GEMM_SMEM>>>();

    cudaFuncSetAttribute(attn_mma_kernel, cudaFuncAttributeMaxDynamicSharedMemorySize, ATTN_SMEM);
    dim3 ga(MM / ABQ, HH);
    attn_mma_kernel<<<ga, 128, ATTN_SMEM>>>(out);
}

// round 13
// speedup vs baseline: 1.0011x; 1.0000x over previous
#include <cuda_runtime.h>
#include <cuda_bf16.h>
#include <cstdint>

// Problem constants
#define MM 1024
#define NN 4096
#define KK 4096
#define HH 32
#define DD 128
#define PP 4096
#define LL (PP + MM)   // 5120

// ---------------- scratch (__device__ globals per alloc rules) ----------------
__device__ __nv_bfloat16 g_Xhi[MM * KK];
__device__ __nv_bfloat16 g_Xlo[MM * KK];
__device__ __nv_bfloat16 g_Wthi[3ull * NN * KK];   // W transposed: [z][n][k]
__device__ __nv_bfloat16 g_Wtlo[3ull * NN * KK];
__device__ __nv_bfloat16 g_Qhi[MM * NN];           // [m][h*128+d]
__device__ __nv_bfloat16 g_Qlo[MM * NN];
__device__ __nv_bfloat16 g_Khi[(size_t)HH * LL * DD];  // [h][p][d]
__device__ __nv_bfloat16 g_Klo[(size_t)HH * LL * DD];
__device__ __nv_bfloat16 g_Vhi[(size_t)HH * LL * DD];
__device__ __nv_bfloat16 g_Vlo[(size_t)HH * LL * DD];

// ================= helpers =================
__device__ __forceinline__ uint32_t smem_to_u32(const void* p) {
    uint32_t a;
    asm("{ .reg .u64 t; cvta.to.shared.u64 t, %1; cvt.u32.u64 %0, t; }" : "=r"(a) : "l"(p));
    return a;
}
__device__ __forceinline__ void cp_async16(uint32_t saddr, const void* gaddr) {
    asm volatile("cp.async.cg.shared.global [%0], [%1], 16;" :: "r"(saddr), "l"(gaddr) : "memory");
}
#define CP_COMMIT() asm volatile("cp.async.commit_group;" ::: "memory")
#define CP_WAIT(n)  asm volatile("cp.async.wait_group %0;" :: "n"(n) : "memory")

__device__ __forceinline__ void ldsm_x4(uint32_t* r, uint32_t addr) {
    asm volatile("ldmatrix.sync.aligned.m8n8.x4.shared.b16 {%0,%1,%2,%3}, [%4];"
                 : "=r"(r[0]), "=r"(r[1]), "=r"(r[2]), "=r"(r[3]) : "r"(addr));
}
__device__ __forceinline__ void ldsm_x4t(uint32_t* r, uint32_t addr) {
    asm volatile("ldmatrix.sync.aligned.m8n8.x4.trans.shared.b16 {%0,%1,%2,%3}, [%4];"
                 : "=r"(r[0]), "=r"(r[1]), "=r"(r[2]), "=r"(r[3]) : "r"(addr));
}
__device__ __forceinline__ void mma16816(float* d, const uint32_t* a, const uint32_t* b) {
    asm volatile(
        "mma.sync.aligned.m16n8k16.row.col.f32.bf16.bf16.f32 "
        "{%0,%1,%2,%3}, {%4,%5,%6,%7}, {%8,%9}, {%0,%1,%2,%3};"
        : "+f"(d[0]), "+f"(d[1]), "+f"(d[2]), "+f"(d[3])
        : "r"(a[0]), "r"(a[1]), "r"(a[2]), "r"(a[3]), "r"(b[0]), "r"(b[1]));
}
__device__ __forceinline__ uint32_t pkbf(float x, float y) {
    __nv_bfloat162 t;
    t.x = __float2bfloat16(x);
    t.y = __float2bfloat16(y);
    return *reinterpret_cast<uint32_t*>(&t);
}

// ================= conversion kernels =================
__global__ __launch_bounds__(256)
void convert_x_kernel(const float* __restrict__ X) {
    int i = (blockIdx.x * 256 + threadIdx.x) * 4;
    float4 v = *(const float4*)(X + i);
    float f[4] = {v.x, v.y, v.z, v.w};
    __align__(8) __nv_bfloat16 hi[4];
    __align__(8) __nv_bfloat16 lo[4];
#pragma unroll
    for (int j = 0; j < 4; j++) {
        hi[j] = __float2bfloat16(f[j]);
        lo[j] = __float2bfloat16(f[j] - __bfloat162float(hi[j]));
    }
    *(uint2*)&g_Xhi[i] = *(uint2*)hi;
    *(uint2*)&g_Xlo[i] = *(uint2*)lo;
}

__global__ __launch_bounds__(256)
void convert_w_kernel(const float* __restrict__ Wq, const float* __restrict__ Wk,
                      const float* __restrict__ Wv) {
    const int z = blockIdx.z;
    const float* W = (z == 0) ? Wq : (z == 1) ? Wk : Wv;
    __shared__ float t[32][33];
    const int n0 = blockIdx.x * 32;
    const int k0 = blockIdx.y * 32;
    const int tx = threadIdx.x;
    const int ty = threadIdx.y;
#pragma unroll
    for (int i = 0; i < 4; i++)
        t[ty + i * 8][tx] = W[(size_t)(k0 + ty + i * 8) * NN + n0 + tx];
    __syncthreads();
    size_t base = (size_t)z * NN * KK;
#pragma unroll
    for (int i = 0; i < 4; i++) {
        int r = ty + i * 8;
        float v = t[tx][r];
        __nv_bfloat16 h = __float2bfloat16(v);
        __nv_bfloat16 l = __float2bfloat16(v - __bfloat162float(h));
        size_t o = base + (size_t)(n0 + r) * KK + k0 + tx;
        g_Wthi[o] = h;
        g_Wtlo[o] = l;
    }
}

__global__ __launch_bounds__(256)
void convert_cache_kernel(const float* __restrict__ cK, const float* __restrict__ cV) {
    const float* src = (blockIdx.y == 0) ? cK : cV;
    __nv_bfloat16* dhi = (blockIdx.y == 0) ? g_Khi : g_Vhi;
    __nv_bfloat16* dlo = (blockIdx.y == 0) ? g_Klo : g_Vlo;
    size_t i = ((size_t)blockIdx.x * 256 + threadIdx.x) * 4;
    float4 v = *(const float4*)(src + i);
    float f[4] = {v.x, v.y, v.z, v.w};
    __align__(8) __nv_bfloat16 hi[4];
    __align__(8) __nv_bfloat16 lo[4];
#pragma unroll
    for (int j = 0; j < 4; j++) {
        hi[j] = __float2bfloat16(f[j]);
        lo[j] = __float2bfloat16(f[j] - __bfloat162float(hi[j]));
    }
    size_t h = i >> 19;
    size_t inner = i & ((size_t)(PP * DD) - 1);
    size_t o = h * ((size_t)LL * DD) + inner;
    *(uint2*)&dhi[o] = *(uint2*)hi;
    *(uint2*)&dlo[o] = *(uint2*)lo;
}

// ================= split-bf16 mma.sync GEMM: proj = X @ W =================
// grid = (NN/128, MM/128, 3); block = 256 (2x4 warps); 3-stage cp.async ring
#define GBM 128
#define GBN 128
#define GBK 32
#define NCHUNK (KK / GBK)

#define ST_AHI 0
#define ST_ALO 8192
#define ST_BHI 16384
#define ST_BLO 24576
#define STAGE_SZ 32768
#define GEMM_SMEM (3 * STAGE_SZ)

__device__ __forceinline__ uint32_t sw_off32(int row, int seg) {   // [rows][32 bf16] 64B rows
    return (uint32_t)(row * 64 + ((seg ^ (row & 3)) << 4));
}

__global__ __launch_bounds__(256, 2)
void qkv_gemm_mma() {
    extern __shared__ char smem[];
    const uint32_t sb = smem_to_u32(smem);
    const int tid = threadIdx.x;
    const int wid = tid >> 5;
    const int lane = tid & 31;
    const int wm = wid >> 2;
    const int wn = wid & 3;
    const int z = blockIdx.z;
    const int row0 = blockIdx.y * GBM;
    const int col0 = blockIdx.x * GBN;
    const int head = blockIdx.x;

    const __nv_bfloat16* Ahi = g_Xhi + (size_t)row0 * KK;
    const __nv_bfloat16* Alo = g_Xlo + (size_t)row0 * KK;
    const __nv_bfloat16* Bhi = g_Wthi + (size_t)z * NN * KK + (size_t)col0 * KK;
    const __nv_bfloat16* Blo = g_Wtlo + (size_t)z * NN * KK + (size_t)col0 * KK;

    const int lr0 = tid >> 2, ls0 = (tid & 3);
    const int lr1 = (tid + 256) >> 2, ls1 = ls0;

    auto load_stage = [&](int s, int k0) {
        uint32_t stb = sb + s * STAGE_SZ;
        const size_t go0 = (size_t)lr0 * KK + k0 + ls0 * 8;
        const size_t go1 = (size_t)lr1 * KK + k0 + ls1 * 8;
        uint32_t so0 = sw_off32(lr0, ls0), so1 = sw_off32(lr1, ls1);
        cp_async16(stb + ST_AHI + so0, Ahi + go0);
        cp_async16(stb + ST_AHI + so1, Ahi + go1);
        cp_async16(stb + ST_ALO + so0, Alo + go0);
        cp_async16(stb + ST_ALO + so1, Alo + go1);
        cp_async16(stb + ST_BHI + so0, Bhi + go0);
        cp_async16(stb + ST_BHI + so1, Bhi + go1);
        cp_async16(stb + ST_BLO + so0, Blo + go0);
        cp_async16(stb + ST_BLO + so1, Blo + go1);
    };

    float acc[4][4][4] = {};

    load_stage(0, 0);
    CP_COMMIT();
    load_stage(1, GBK);
    CP_COMMIT();

    // per-lane ldmatrix address components
    const int a_row = (lane & 15);
    const int a_seg = (lane >> 4);
    const int b_row4 = ((lane >> 4) & 1) * 8 + (lane & 7);   // x4: pair of n-frags
    const int b_seg4 = (lane >> 3) & 1;

    int s = 0, sl = 2;
    for (int c = 0; c < NCHUNK; ++c) {
        CP_WAIT(1);                 // positional: all but most recent group done -> chunk c ready
        __syncthreads();            // visibility + stage-reuse guard
        if (c + 2 < NCHUNK) load_stage(sl, (c + 2) * GBK);
        CP_COMMIT();                // always commit (empty at tail keeps positions aligned)

        const uint32_t stb = sb + s * STAGE_SZ;
#pragma unroll
        for (int ks = 0; ks < 2; ++ks) {
            const int segb = ks * 2;
            uint32_t ahi[4][4], alo[4][4], bhi[2][4], blo[2][4];
#pragma unroll
            for (int mf = 0; mf < 4; ++mf) {
                uint32_t off = sw_off32(wm * 64 + mf * 16 + a_row, segb + a_seg);
                ldsm_x4(ahi[mf], stb + ST_AHI + off);
                ldsm_x4(alo[mf], stb + ST_ALO + off);
            }
#pragma unroll
            for (int np = 0; np < 2; ++np) {
                uint32_t off = sw_off32(wn * 32 + np * 16 + b_row4, segb + b_seg4);
                ldsm_x4(bhi[np], stb + ST_BHI + off);
                ldsm_x4(blo[np], stb + ST_BLO + off);
            }
#pragma unroll
            for (int mf = 0; mf < 4; ++mf)
#pragma unroll
                for (int nf = 0; nf < 4; ++nf) {
                    const uint32_t* bh = bhi[nf >> 1] + (nf & 1) * 2;
                    const uint32_t* bl = blo[nf >> 1] + (nf & 1) * 2;
                    mma16816(acc[mf][nf], ahi[mf], bh);
                    mma16816(acc[mf][nf], ahi[mf], bl);
                    mma16816(acc[mf][nf], alo[mf], bh);
                }
        }
        s = (s == 2) ? 0 : s + 1;
        sl = (sl == 2) ? 0 : sl + 1;
    }

    // epilogue: write split-bf16 directly
    const int erow = lane >> 2;
    const int ecol = (lane & 3) * 2;
#pragma unroll
    for (int mf = 0; mf < 4; ++mf) {
#pragma unroll
        for (int nf = 0; nf < 4; ++nf) {
            int cloc = wn * 32 + nf * 8 + ecol;
#pragma unroll
            for (int rr = 0; rr < 2; ++rr) {
                int rowg = row0 + wm * 64 + mf * 16 + erow + rr * 8;
                float v0 = acc[mf][nf][rr * 2 + 0];
                float v1 = acc[mf][nf][rr * 2 + 1];
                __nv_bfloat16 h0 = __float2bfloat16(v0);
                __nv_bfloat16 h1 = __float2bfloat16(v1);
                float l0 = v0 - __bfloat162float(h0);
                float l1 = v1 - __bfloat162float(h1);
                uint32_t ph = pkbf(__bfloat162float(h0), __bfloat162float(h1));
                uint32_t pl = pkbf(l0, l1);
                if (z == 0) {
                    size_t o = (size_t)rowg * NN + col0 + cloc;
                    *(uint32_t*)&g_Qhi[o] = ph;
                    *(uint32_t*)&g_Qlo[o] = pl;
                } else {
                    size_t o = ((size_t)head * LL + PP + rowg) * DD + cloc;
                    if (z == 1) { *(uint32_t*)&g_Khi[o] = ph; *(uint32_t*)&g_Klo[o] = pl; }
                    else        { *(uint32_t*)&g_Vhi[o] = ph; *(uint32_t*)&g_Vlo[o] = pl; }
                }
            }
        }
    }
}

// ================= tensor-core flash attention (split bf16, 3-pass) =================
// grid = (MM/64, HH); block = 128 (4 warps); smem 96KB, 2 CTAs/SM
#define ABQ 64
#define ATK 64
#define NT_KV (LL / ATK)   // 80

#define AQH 0
#define AQL 16384
#define AKH 32768
#define AKL 49152
#define AVH 65536
#define AVL 81920
#define ATTN_SMEM 98304

__device__ __forceinline__ uint32_t sw_off128(int row, int seg) {  // [rows][128 bf16] 256B rows
    return (uint32_t)(row * 256 + ((seg ^ (row & 7)) << 4));
}

__global__ __launch_bounds__(128, 2)
void attn_mma_kernel(float* __restrict__ out) {
    extern __shared__ char smem[];
    const uint32_t sb = smem_to_u32(smem);
    const int tid = threadIdx.x;
    const int lane = tid & 31;
    const int wq = tid >> 5;
    const int h = blockIdx.y;
    const int q0 = blockIdx.x * ABQ;

    const __nv_bfloat16* Kh = g_Khi + (size_t)h * LL * DD;
    const __nv_bfloat16* Kl = g_Klo + (size_t)h * LL * DD;
    const __nv_bfloat16* Vh = g_Vhi + (size_t)h * LL * DD;
    const __nv_bfloat16* Vl = g_Vlo + (size_t)h * LL * DD;

    // Q load (group 0)
#pragma unroll
    for (int i = 0; i < 8; i++) {
        int idx = tid + i * 128;
        int row = idx >> 4, seg = idx & 15;
        uint32_t so = sw_off128(row, seg);
        size_t go = (size_t)(q0 + row) * NN + h * DD + seg * 8;
        cp_async16(sb + AQH + so, g_Qhi + go);
        cp_async16(sb + AQL + so, g_Qlo + go);
    }
    CP_COMMIT();

    auto load_kv = [&](uint32_t dH, uint32_t dL, const __nv_bfloat16* sH,
                       const __nv_bfloat16* sL, int p0) {
#pragma unroll
        for (int i = 0; i < 8; i++) {
            int idx = tid + i * 128;
            int row = idx >> 4, seg = idx & 15;
            uint32_t so = sw_off128(row, seg);
            size_t go = (size_t)(p0 + row) * DD + seg * 8;
            cp_async16(dH + so, sH + go);
            cp_async16(dL + so, sL + go);
        }
    };

    load_kv(sb + AKH, sb + AKL, Kh, Kl, 0);  CP_COMMIT();   // K0
    load_kv(sb + AVH, sb + AVL, Vh, Vl, 0);  CP_COMMIT();   // V0

    float oacc[16][4] = {};
    float m_s[2] = {-1e30f, -1e30f};
    float l_s[2] = {0.0f, 0.0f};

    const int a_row = wq * 16 + (lane & 15);
    const int b_row = ((lane >> 4) & 1) * 8 + (lane & 7);
    const int bsegl = (lane >> 3) & 1;
    const int v_row = ((lane >> 3) & 1) * 8 + (lane & 7);
    const int v_seg = lane >> 4;

    for (int t = 0; t < NT_KV; ++t) {
        CP_WAIT(1);                 // K(t) ready (V(t) may be in flight)
        __syncthreads();

        // ---- S = Q K^T tile (16 x 64 per warp), 3-pass split ----
        float sacc[8][4] = {};
#pragma unroll
        for (int ksd = 0; ksd < 8; ++ksd) {
            uint32_t ah[4], al[4];
            uint32_t aoff = sw_off128(a_row, ksd * 2 + (lane >> 4));
            ldsm_x4(ah, sb + AQH + aoff);
            ldsm_x4(al, sb + AQL + aoff);
#pragma unroll
            for (int j = 0; j < 4; ++j) {
                uint32_t bh[4], bl[4];
                uint32_t boff = sw_off128(j * 16 + b_row, ksd * 2 + bsegl);
                ldsm_x4(bh, sb + AKH + boff);
                ldsm_x4(bl, sb + AKL + boff);
                mma16816(sacc[2 * j], ah, bh);
                mma16816(sacc[2 * j], ah, bl);
                mma16816(sacc[2 * j], al, bh);
                mma16816(sacc[2 * j + 1], ah, bh + 2);
                mma16816(sacc[2 * j + 1], ah, bl + 2);
                mma16816(sacc[2 * j + 1], al, bh + 2);
            }
        }
        __syncthreads();            // all warps done reading K(t)
        if (t + 1 < NT_KV) load_kv(sb + AKH, sb + AKL, Kh, Kl, (t + 1) * ATK);
        CP_COMMIT();                // K(t+1) (or empty)

        // ---- online softmax + P conversion (registers only; overlaps K(t+1) load) ----
        uint32_t pa_hi[16], pa_lo[16];
#pragma unroll
        for (int rh = 0; rh < 2; ++rh) {
            float mx = -1e30f;
#pragma unroll
            for (int nt = 0; nt < 8; ++nt)
                mx = fmaxf(mx, fmaxf(sacc[nt][rh * 2], sacc[nt][rh * 2 + 1]));
            mx = fmaxf(mx, __shfl_xor_sync(0xffffffffu, mx, 1));
            mx = fmaxf(mx, __shfl_xor_sync(0xffffffffu, mx, 2));
            float mnew = fmaxf(m_s[rh], mx);
            float sc = __expf(m_s[rh] - mnew);
            m_s[rh] = mnew;
            float sum = 0.0f;
#pragma unroll
            for (int nt = 0; nt < 8; ++nt) {
                float e0 = __expf(sacc[nt][rh * 2] - mnew);
                float e1 = __expf(sacc[nt][rh * 2 + 1] - mnew);
                sacc[nt][rh * 2] = e0;
                sacc[nt][rh * 2 + 1] = e1;
                sum += e0 + e1;
            }
            sum += __shfl_xor_sync(0xffffffffu, sum, 1);
            sum += __shfl_xor_sync(0xffffffffu, sum, 2);
            l_s[rh] = l_s[rh] * sc + sum;
#pragma unroll
            for (int dt = 0; dt < 16; ++dt) {
                oacc[dt][rh * 2] *= sc;
                oacc[dt][rh * 2 + 1] *= sc;
            }
        }
#pragma unroll
        for (int ks = 0; ks < 4; ++ks) {
#pragma unroll
            for (int half = 0; half < 2; ++half) {
                int nt = 2 * ks + half;
#pragma unroll
                for (int rh = 0; rh < 2; ++rh) {
                    float v0 = sacc[nt][rh * 2], v1 = sacc[nt][rh * 2 + 1];
                    __nv_bfloat16 h0 = __float2bfloat16(v0);
                    __nv_bfloat16 h1 = __float2bfloat16(v1);
                    pa_hi[ks * 4 + half * 2 + rh] = pkbf(__bfloat162float(h0), __bfloat162float(h1));
                    pa_lo[ks * 4 + half * 2 + rh] =
                        pkbf(v0 - __bfloat162float(h0), v1 - __bfloat162float(h1));
                }
            }
        }

        CP_WAIT(1);                 // V(t) ready (K(t+1) may be in flight)
        __syncthreads();

        // ---- O += P V (3-pass split) ----
#pragma unroll
        for (int ks = 0; ks < 4; ++ks) {
            const uint32_t* ph = pa_hi + ks * 4;
            const uint32_t* pl = pa_lo + ks * 4;
#pragma unroll
            for (int dt2 = 0; dt2 < 8; ++dt2) {
                uint32_t vh[4], vl[4];
                uint32_t voff = sw_off128(ks * 16 + v_row, dt2 * 2 + v_seg);
                ldsm_x4t(vh, sb + AVH + voff);
                ldsm_x4t(vl, sb + AVL + voff);
                mma16816(oacc[2 * dt2], ph, vh);
                mma16816(oacc[2 * dt2], ph, vl);
                mma16816(oacc[2 * dt2], pl, vh);
                mma16816(oacc[2 * dt2 + 1], ph, vh + 2);
                mma16816(oacc[2 * dt2 + 1], ph, vl + 2);
                mma16816(oacc[2 * dt2 + 1], pl, vh + 2);
            }
        }
        __syncthreads();            // all warps done reading V(t)
        if (t + 1 < NT_KV) load_kv(sb + AVH, sb + AVL, Vh, Vl, (t + 1) * ATK);
        CP_COMMIT();                // V(t+1) (or empty)
    }

    // ---- epilogue ----
    const int g = lane >> 2;
    const int tg = lane & 3;
    float inv0 = 1.0f / l_s[0];
    float inv1 = 1.0f / l_s[1];
    int row0 = q0 + wq * 16 + g;
#pragma unroll
    for (int dt = 0; dt < 16; ++dt) {
        int col = h * DD + dt * 8 + tg * 2;
        *(float2*)&out[(size_t)row0 * NN + col] =
            make_float2(oacc[dt][0] * inv0, oacc[dt][1] * inv0);
        *(float2*)&out[(size_t)(row0 + 8) * NN + col] =
            make_float2(oacc[dt][2] * inv1, oacc[dt][3] * inv1);
    }
}

// ================= launch =================
extern "C" void kernel_launch(void* const* d_in, const int* in_sizes, int n_in,
                              void* d_out, int out_size) {
    const float* X  = (const float*)d_in[0];
    const float* Wq = (const float*)d_in[1];
    const float* Wk = (const float*)d_in[2];
    const float* Wv = (const float*)d_in[3];
    const float* cK = (const float*)d_in[4];
    const float* cV = (const float*)d_in[5];
    float* out = (float*)d_out;

    convert_x_kernel<<<(MM * KK) / (4 * 256), 256>>>(X);
    dim3 gw(NN / 32, KK / 32, 3);
    convert_w_kernel<<<gw, dim3(32, 8)>>>(Wq, Wk, Wv);
    dim3 gc((unsigned)(((size_t)HH * PP * DD) / (4 * 256)), 2);
    convert_cache_kernel<<<gc, 256>>>(cK, cV);

    cudaFuncSetAttribute(qkv_gemm_mma, cudaFuncAttributeMaxDynamicSharedMemorySize, GEMM_SMEM);
    dim3 gg(NN / GBN, MM / GBM, 3);
    qkv_gemm_mma<<<gg, 256, GEMM_SMEM>>>();

    cudaFuncSetAttribute(attn_mma_kernel, cudaFuncAttributeMaxDynamicSharedMemorySize, ATTN_SMEM);
    dim3 ga(MM / ABQ, HH);
    attn_mma_kernel<<<ga, 128, ATTN_SMEM>>>(out);
}

// round 14
// speedup vs baseline: 1.0012x; 1.0002x over previous
#include <cuda_runtime.h>
#include <cuda_bf16.h>
#include <cstdint>

// Problem constants
#define MM 1024
#define NN 4096
#define KK 4096
#define HH 32
#define DD 128
#define PP 4096
#define LL (PP + MM)   // 5120

// ---------------- scratch (__device__ globals per alloc rules) ----------------
__device__ __nv_bfloat16 g_Xhi[MM * KK];
__device__ __nv_bfloat16 g_Xlo[MM * KK];
__device__ __nv_bfloat16 g_Wthi[3ull * NN * KK];   // W transposed: [z][n][k]
__device__ __nv_bfloat16 g_Wtlo[3ull * NN * KK];
__device__ __nv_bfloat16 g_Qhi[MM * NN];           // [m][h*128+d]
__device__ __nv_bfloat16 g_Qlo[MM * NN];
__device__ __nv_bfloat16 g_Khi[(size_t)HH * LL * DD];  // [h][p][d]
__device__ __nv_bfloat16 g_Klo[(size_t)HH * LL * DD];
__device__ __nv_bfloat16 g_Vhi[(size_t)HH * LL * DD];
__device__ __nv_bfloat16 g_Vlo[(size_t)HH * LL * DD];

// ================= helpers =================
__device__ __forceinline__ uint32_t smem_to_u32(const void* p) {
    uint32_t a;
    asm("{ .reg .u64 t; cvta.to.shared.u64 t, %1; cvt.u32.u64 %0, t; }" : "=r"(a) : "l"(p));
    return a;
}
__device__ __forceinline__ void cp_async16(uint32_t saddr, const void* gaddr) {
    asm volatile("cp.async.cg.shared.global [%0], [%1], 16;" :: "r"(saddr), "l"(gaddr) : "memory");
}
#define CP_COMMIT() asm volatile("cp.async.commit_group;" ::: "memory")
#define CP_WAIT(n)  asm volatile("cp.async.wait_group %0;" :: "n"(n) : "memory")

__device__ __forceinline__ void ldsm_x4(uint32_t* r, uint32_t addr) {
    asm volatile("ldmatrix.sync.aligned.m8n8.x4.shared.b16 {%0,%1,%2,%3}, [%4];"
                 : "=r"(r[0]), "=r"(r[1]), "=r"(r[2]), "=r"(r[3]) : "r"(addr));
}
__device__ __forceinline__ void ldsm_x4t(uint32_t* r, uint32_t addr) {
    asm volatile("ldmatrix.sync.aligned.m8n8.x4.trans.shared.b16 {%0,%1,%2,%3}, [%4];"
                 : "=r"(r[0]), "=r"(r[1]), "=r"(r[2]), "=r"(r[3]) : "r"(addr));
}
__device__ __forceinline__ void mma16816(float* d, const uint32_t* a, const uint32_t* b) {
    asm volatile(
        "mma.sync.aligned.m16n8k16.row.col.f32.bf16.bf16.f32 "
        "{%0,%1,%2,%3}, {%4,%5,%6,%7}, {%8,%9}, {%0,%1,%2,%3};"
        : "+f"(d[0]), "+f"(d[1]), "+f"(d[2]), "+f"(d[3])
        : "r"(a[0]), "r"(a[1]), "r"(a[2]), "r"(a[3]), "r"(b[0]), "r"(b[1]));
}
__device__ __forceinline__ uint32_t pkbf(float x, float y) {
    __nv_bfloat162 t;
    t.x = __float2bfloat16(x);
    t.y = __float2bfloat16(y);
    return *reinterpret_cast<uint32_t*>(&t);
}

// ================= conversion kernels =================
__global__ __launch_bounds__(256)
void convert_x_kernel(const float* __restrict__ X) {
    int i = (blockIdx.x * 256 + threadIdx.x) * 4;
    float4 v = *(const float4*)(X + i);
    float f[4] = {v.x, v.y, v.z, v.w};
    __align__(8) __nv_bfloat16 hi[4];
    __align__(8) __nv_bfloat16 lo[4];
#pragma unroll
    for (int j = 0; j < 4; j++) {
        hi[j] = __float2bfloat16(f[j]);
        lo[j] = __float2bfloat16(f[j] - __bfloat162float(hi[j]));
    }
    *(uint2*)&g_Xhi[i] = *(uint2*)hi;
    *(uint2*)&g_Xlo[i] = *(uint2*)lo;
}

__global__ __launch_bounds__(256)
void convert_w_kernel(const float* __restrict__ Wq, const float* __restrict__ Wk,
                      const float* __restrict__ Wv) {
    const int z = blockIdx.z;
    const float* W = (z == 0) ? Wq : (z == 1) ? Wk : Wv;
    __shared__ float t[32][33];
    const int n0 = blockIdx.x * 32;
    const int k0 = blockIdx.y * 32;
    const int tx = threadIdx.x;
    const int ty = threadIdx.y;
#pragma unroll
    for (int i = 0; i < 4; i++)
        t[ty + i * 8][tx] = W[(size_t)(k0 + ty + i * 8) * NN + n0 + tx];
    __syncthreads();
    size_t base = (size_t)z * NN * KK;
#pragma unroll
    for (int i = 0; i < 4; i++) {
        int r = ty + i * 8;
        float v = t[tx][r];
        __nv_bfloat16 h = __float2bfloat16(v);
        __nv_bfloat16 l = __float2bfloat16(v - __bfloat162float(h));
        size_t o = base + (size_t)(n0 + r) * KK + k0 + tx;
        g_Wthi[o] = h;
        g_Wtlo[o] = l;
    }
}

__global__ __launch_bounds__(256)
void convert_cache_kernel(const float* __restrict__ cK, const float* __restrict__ cV) {
    const float* src = (blockIdx.y == 0) ? cK : cV;
    __nv_bfloat16* dhi = (blockIdx.y == 0) ? g_Khi : g_Vhi;
    __nv_bfloat16* dlo = (blockIdx.y == 0) ? g_Klo : g_Vlo;
    size_t i = ((size_t)blockIdx.x * 256 + threadIdx.x) * 4;
    float4 v = *(const float4*)(src + i);
    float f[4] = {v.x, v.y, v.z, v.w};
    __align__(8) __nv_bfloat16 hi[4];
    __align__(8) __nv_bfloat16 lo[4];
#pragma unroll
    for (int j = 0; j < 4; j++) {
        hi[j] = __float2bfloat16(f[j]);
        lo[j] = __float2bfloat16(f[j] - __bfloat162float(hi[j]));
    }
    size_t h = i >> 19;
    size_t inner = i & ((size_t)(PP * DD) - 1);
    size_t o = h * ((size_t)LL * DD) + inner;
    *(uint2*)&dhi[o] = *(uint2*)hi;
    *(uint2*)&dlo[o] = *(uint2*)lo;
}

// ================= split-bf16 mma.sync GEMM: proj = X @ W =================
// grid = (NN/128, MM/128, 3); block = 256 (2x4 warps); 3-stage cp.async ring
#define GBM 128
#define GBN 128
#define GBK 32
#define NCHUNK (KK / GBK)

#define ST_AHI 0
#define ST_ALO 8192
#define ST_BHI 16384
#define ST_BLO 24576
#define STAGE_SZ 32768
#define GEMM_SMEM (3 * STAGE_SZ)

__device__ __forceinline__ uint32_t sw_off32(int row, int seg) {   // [rows][32 bf16] 64B rows
    return (uint32_t)(row * 64 + ((seg ^ (row & 3)) << 4));
}

__global__ __launch_bounds__(256, 2)
void qkv_gemm_mma() {
    extern __shared__ char smem[];
    const uint32_t sb = smem_to_u32(smem);
    const int tid = threadIdx.x;
    const int wid = tid >> 5;
    const int lane = tid & 31;
    const int wm = wid >> 2;
    const int wn = wid & 3;
    const int z = blockIdx.z;
    const int row0 = blockIdx.y * GBM;
    const int col0 = blockIdx.x * GBN;
    const int head = blockIdx.x;

    const __nv_bfloat16* Ahi = g_Xhi + (size_t)row0 * KK;
    const __nv_bfloat16* Alo = g_Xlo + (size_t)row0 * KK;
    const __nv_bfloat16* Bhi = g_Wthi + (size_t)z * NN * KK + (size_t)col0 * KK;
    const __nv_bfloat16* Blo = g_Wtlo + (size_t)z * NN * KK + (size_t)col0 * KK;

    const int lr0 = tid >> 2, ls0 = (tid & 3);
    const int lr1 = (tid + 256) >> 2, ls1 = ls0;

    auto load_stage = [&](int s, int k0) {
        uint32_t stb = sb + s * STAGE_SZ;
        const size_t go0 = (size_t)lr0 * KK + k0 + ls0 * 8;
        const size_t go1 = (size_t)lr1 * KK + k0 + ls1 * 8;
        uint32_t so0 = sw_off32(lr0, ls0), so1 = sw_off32(lr1, ls1);
        cp_async16(stb + ST_AHI + so0, Ahi + go0);
        cp_async16(stb + ST_AHI + so1, Ahi + go1);
        cp_async16(stb + ST_ALO + so0, Alo + go0);
        cp_async16(stb + ST_ALO + so1, Alo + go1);
        cp_async16(stb + ST_BHI + so0, Bhi + go0);
        cp_async16(stb + ST_BHI + so1, Bhi + go1);
        cp_async16(stb + ST_BLO + so0, Blo + go0);
        cp_async16(stb + ST_BLO + so1, Blo + go1);
    };

    float acc[4][4][4] = {};

    load_stage(0, 0);
    CP_COMMIT();
    load_stage(1, GBK);
    CP_COMMIT();

    // per-lane ldmatrix address components
    const int a_row = (lane & 15);
    const int a_seg = (lane >> 4);
    const int b_row4 = ((lane >> 4) & 1) * 8 + (lane & 7);   // x4: pair of n-frags
    const int b_seg4 = (lane >> 3) & 1;

    int s = 0, sl = 2;
    for (int c = 0; c < NCHUNK; ++c) {
        CP_WAIT(1);                 // positional: all but most recent group done -> chunk c ready
        __syncthreads();            // visibility + stage-reuse guard
        if (c + 2 < NCHUNK) load_stage(sl, (c + 2) * GBK);
        CP_COMMIT();                // always commit (empty at tail keeps positions aligned)

        const uint32_t stb = sb + s * STAGE_SZ;
#pragma unroll
        for (int ks = 0; ks < 2; ++ks) {
            const int segb = ks * 2;
            uint32_t ahi[4][4], alo[4][4], bhi[2][4], blo[2][4];
#pragma unroll
            for (int mf = 0; mf < 4; ++mf) {
                uint32_t off = sw_off32(wm * 64 + mf * 16 + a_row, segb + a_seg);
                ldsm_x4(ahi[mf], stb + ST_AHI + off);
                ldsm_x4(alo[mf], stb + ST_ALO + off);
            }
#pragma unroll
            for (int np = 0; np < 2; ++np) {
                uint32_t off = sw_off32(wn * 32 + np * 16 + b_row4, segb + b_seg4);
                ldsm_x4(bhi[np], stb + ST_BHI + off);
                ldsm_x4(blo[np], stb + ST_BLO + off);
            }
#pragma unroll
            for (int mf = 0; mf < 4; ++mf)
#pragma unroll
                for (int nf = 0; nf < 4; ++nf) {
                    const uint32_t* bh = bhi[nf >> 1] + (nf & 1) * 2;
                    const uint32_t* bl = blo[nf >> 1] + (nf & 1) * 2;
                    mma16816(acc[mf][nf], ahi[mf], bh);
                    mma16816(acc[mf][nf], ahi[mf], bl);
                    mma16816(acc[mf][nf], alo[mf], bh);
                }
        }
        s = (s == 2) ? 0 : s + 1;
        sl = (sl == 2) ? 0 : sl + 1;
    }

    // epilogue: write split-bf16 directly
    const int erow = lane >> 2;
    const int ecol = (lane & 3) * 2;
#pragma unroll
    for (int mf = 0; mf < 4; ++mf) {
#pragma unroll
        for (int nf = 0; nf < 4; ++nf) {
            int cloc = wn * 32 + nf * 8 + ecol;
#pragma unroll
            for (int rr = 0; rr < 2; ++rr) {
                int rowg = row0 + wm * 64 + mf * 16 + erow + rr * 8;
                float v0 = acc[mf][nf][rr * 2 + 0];
                float v1 = acc[mf][nf][rr * 2 + 1];
                __nv_bfloat16 h0 = __float2bfloat16(v0);
                __nv_bfloat16 h1 = __float2bfloat16(v1);
                float l0 = v0 - __bfloat162float(h0);
                float l1 = v1 - __bfloat162float(h1);
                uint32_t ph = pkbf(__bfloat162float(h0), __bfloat162float(h1));
                uint32_t pl = pkbf(l0, l1);
                if (z == 0) {
                    size_t o = (size_t)rowg * NN + col0 + cloc;
                    *(uint32_t*)&g_Qhi[o] = ph;
                    *(uint32_t*)&g_Qlo[o] = pl;
                } else {
                    size_t o = ((size_t)head * LL + PP + rowg) * DD + cloc;
                    if (z == 1) { *(uint32_t*)&g_Khi[o] = ph; *(uint32_t*)&g_Klo[o] = pl; }
                    else        { *(uint32_t*)&g_Vhi[o] = ph; *(uint32_t*)&g_Vlo[o] = pl; }
                }
            }
        }
    }
}

// ================= tensor-core flash attention (split bf16, 3-pass) =================
// grid = (MM/64, HH); block = 128 (4 warps); smem 96KB, 2 CTAs/SM
#define ABQ 64
#define ATK 64
#define NT_KV (LL / ATK)   // 80

#define AQH 0
#define AQL 16384
#define AKH 32768
#define AKL 49152
#define AVH 65536
#define AVL 81920
#define ATTN_SMEM 98304

__device__ __forceinline__ uint32_t sw_off128(int row, int seg) {  // [rows][128 bf16] 256B rows
    return (uint32_t)(row * 256 + ((seg ^ (row & 7)) << 4));
}

__global__ __launch_bounds__(128, 2)
void attn_mma_kernel(float* __restrict__ out) {
    extern __shared__ char smem[];
    const uint32_t sb = smem_to_u32(smem);
    const int tid = threadIdx.x;
    const int lane = tid & 31;
    const int wq = tid >> 5;
    const int h = blockIdx.y;
    const int q0 = blockIdx.x * ABQ;

    const __nv_bfloat16* Kh = g_Khi + (size_t)h * LL * DD;
    const __nv_bfloat16* Kl = g_Klo + (size_t)h * LL * DD;
    const __nv_bfloat16* Vh = g_Vhi + (size_t)h * LL * DD;
    const __nv_bfloat16* Vl = g_Vlo + (size_t)h * LL * DD;

    // Q load (group 0)
#pragma unroll
    for (int i = 0; i < 8; i++) {
        int idx = tid + i * 128;
        int row = idx >> 4, seg = idx & 15;
        uint32_t so = sw_off128(row, seg);
        size_t go = (size_t)(q0 + row) * NN + h * DD + seg * 8;
        cp_async16(sb + AQH + so, g_Qhi + go);
        cp_async16(sb + AQL + so, g_Qlo + go);
    }
    CP_COMMIT();

    auto load_kv = [&](uint32_t dH, uint32_t dL, const __nv_bfloat16* sH,
                       const __nv_bfloat16* sL, int p0) {
#pragma unroll
        for (int i = 0; i < 8; i++) {
            int idx = tid + i * 128;
            int row = idx >> 4, seg = idx & 15;
            uint32_t so = sw_off128(row, seg);
            size_t go = (size_t)(p0 + row) * DD + seg * 8;
            cp_async16(dH + so, sH + go);
            cp_async16(dL + so, sL + go);
        }
    };

    load_kv(sb + AKH, sb + AKL, Kh, Kl, 0);  CP_COMMIT();   // K0
    load_kv(sb + AVH, sb + AVL, Vh, Vl, 0);  CP_COMMIT();   // V0

    float oacc[16][4] = {};
    float m_s[2] = {-1e30f, -1e30f};
    float l_s[2] = {0.0f, 0.0f};

    const int a_row = wq * 16 + (lane & 15);
    const int b_row = ((lane >> 4) & 1) * 8 + (lane & 7);
    const int bsegl = (lane >> 3) & 1;
    const int v_row = ((lane >> 3) & 1) * 8 + (lane & 7);
    const int v_seg = lane >> 4;

    for (int t = 0; t < NT_KV; ++t) {
        CP_WAIT(1);                 // K(t) ready (V(t) may be in flight)
        __syncthreads();

        // ---- S = Q K^T tile (16 x 64 per warp), 3-pass split ----
        float sacc[8][4] = {};
#pragma unroll
        for (int ksd = 0; ksd < 8; ++ksd) {
            uint32_t ah[4], al[4];
            uint32_t aoff = sw_off128(a_row, ksd * 2 + (lane >> 4));
            ldsm_x4(ah, sb + AQH + aoff);
            ldsm_x4(al, sb + AQL + aoff);
#pragma unroll
            for (int j = 0; j < 4; ++j) {
                uint32_t bh[4], bl[4];
                uint32_t boff = sw_off128(j * 16 + b_row, ksd * 2 + bsegl);
                ldsm_x4(bh, sb + AKH + boff);
                ldsm_x4(bl, sb + AKL + boff);
                mma16816(sacc[2 * j], ah, bh);
                mma16816(sacc[2 * j], ah, bl);
                mma16816(sacc[2 * j], al, bh);
                mma16816(sacc[2 * j + 1], ah, bh + 2);
                mma16816(sacc[2 * j + 1], ah, bl + 2);
                mma16816(sacc[2 * j + 1], al, bh + 2);
            }
        }
        __syncthreads();            // all warps done reading K(t)
        if (t + 1 < NT_KV) load_kv(sb + AKH, sb + AKL, Kh, Kl, (t + 1) * ATK);
        CP_COMMIT();                // K(t+1) (or empty)

        // ---- online softmax + P conversion (registers only; overlaps K(t+1) load) ----
        uint32_t pa_hi[16], pa_lo[16];
#pragma unroll
        for (int rh = 0; rh < 2; ++rh) {
            float mx = -1e30f;
#pragma unroll
            for (int nt = 0; nt < 8; ++nt)
                mx = fmaxf(mx, fmaxf(sacc[nt][rh * 2], sacc[nt][rh * 2 + 1]));
            mx = fmaxf(mx, __shfl_xor_sync(0xffffffffu, mx, 1));
            mx = fmaxf(mx, __shfl_xor_sync(0xffffffffu, mx, 2));
            float mnew = fmaxf(m_s[rh], mx);
            float sc = __expf(m_s[rh] - mnew);
            m_s[rh] = mnew;
            float sum = 0.0f;
#pragma unroll
            for (int nt = 0; nt < 8; ++nt) {
                float e0 = __expf(sacc[nt][rh * 2] - mnew);
                float e1 = __expf(sacc[nt][rh * 2 + 1] - mnew);
                sacc[nt][rh * 2] = e0;
                sacc[nt][rh * 2 + 1] = e1;
                sum += e0 + e1;
            }
            sum += __shfl_xor_sync(0xffffffffu, sum, 1);
            sum += __shfl_xor_sync(0xffffffffu, sum, 2);
            l_s[rh] = l_s[rh] * sc + sum;
#pragma unroll
            for (int dt = 0; dt < 16; ++dt) {
                oacc[dt][rh * 2] *= sc;
                oacc[dt][rh * 2 + 1] *= sc;
            }
        }
#pragma unroll
        for (int ks = 0; ks < 4; ++ks) {
#pragma unroll
            for (int half = 0; half < 2; ++half) {
                int nt = 2 * ks + half;
#pragma unroll
                for (int rh = 0; rh < 2; ++rh) {
                    float v0 = sacc[nt][rh * 2], v1 = sacc[nt][rh * 2 + 1];
                    __nv_bfloat16 h0 = __float2bfloat16(v0);
                    __nv_bfloat16 h1 = __float2bfloat16(v1);
                    pa_hi[ks * 4 + half * 2 + rh] = pkbf(__bfloat162float(h0), __bfloat162float(h1));
                    pa_lo[ks * 4 + half * 2 + rh] =
                        pkbf(v0 - __bfloat162float(h0), v1 - __bfloat162float(h1));
                }
            }
        }

        CP_WAIT(1);                 // V(t) ready (K(t+1) may be in flight)
        __syncthreads();

        // ---- O += P V (3-pass split) ----
#pragma unroll
        for (int ks = 0; ks < 4; ++ks) {
            const uint32_t* ph = pa_hi + ks * 4;
            const uint32_t* pl = pa_lo + ks * 4;
#pragma unroll
            for (int dt2 = 0; dt2 < 8; ++dt2) {
                uint32_t vh[4], vl[4];
                uint32_t voff = sw_off128(ks * 16 + v_row, dt2 * 2 + v_seg);
                ldsm_x4t(vh, sb + AVH + voff);
                ldsm_x4t(vl, sb + AVL + voff);
                mma16816(oacc[2 * dt2], ph, vh);
                mma16816(oacc[2 * dt2], ph, vl);
                mma16816(oacc[2 * dt2], pl, vh);
                mma16816(oacc[2 * dt2 + 1], ph, vh + 2);
                mma16816(oacc[2 * dt2 + 1], ph, vl + 2);
                mma16816(oacc[2 * dt2 + 1], pl, vh + 2);
            }
        }
        __syncthreads();            // all warps done reading V(t)
        if (t + 1 < NT_KV) load_kv(sb + AVH, sb + AVL, Vh, Vl, (t + 1) * ATK);
        CP_COMMIT();                // V(t+1) (or empty)
    }

    // ---- epilogue ----
    const int g = lane >> 2;
    const int tg = lane & 3;
    float inv0 = 1.0f / l_s[0];
    float inv1 = 1.0f / l_s[1];
    int row0 = q0 + wq * 16 + g;
#pragma unroll
    for (int dt = 0; dt < 16; ++dt) {
        int col = h * DD + dt * 8 + tg * 2;
        *(float2*)&out[(size_t)row0 * NN + col] =
            make_float2(oacc[dt][0] * inv0, oacc[dt][1] * inv0);
        *(float2*)&out[(size_t)(row0 + 8) * NN + col] =
            make_float2(oacc[dt][2] * inv1, oacc[dt][3] * inv1);
    }
}

// ================= launch =================
extern "C" void kernel_launch(void* const* d_in, const int* in_sizes, int n_in,
                              void* d_out, int out_size) {
    const float* X  = (const float*)d_in[0];
    const float* Wq = (const float*)d_in[1];
    const float* Wk = (const float*)d_in[2];
    const float* Wv = (const float*)d_in[3];
    const float* cK = (const float*)d_in[4];
    const float* cV = (const float*)d_in[5];
    float* out = (float*)d_out;

    convert_x_kernel<<<(MM * KK) / (4 * 256), 256>>>(X);
    dim3 gw(NN / 32, KK / 32, 3);
    convert_w_kernel<<<gw, dim3(32, 8)>>>(Wq, Wk, Wv);
    dim3 gc((unsigned)(((size_t)HH * PP * DD) / (4 * 256)), 2);
    convert_cache_kernel<<<gc, 256>>>(cK, cV);

    cudaFuncSetAttribute(qkv_gemm_mma, cudaFuncAttributeMaxDynamicSharedMemorySize, GEMM_SMEM);
    dim3 gg(NN / GBN, MM / GBM, 3);
    qkv_gemm_mma<<<gg, 256, GEMM_SMEM>>>();

    cudaFuncSetAttribute(attn_mma_kernel, cudaFuncAttributeMaxDynamicSharedMemorySize, ATTN_SMEM);
    dim3 ga(MM / ABQ, HH);
    attn_mma_kernel<<<ga, 128, ATTN_SMEM>>>(out);
}